// round 4
// baseline (speedup 1.0000x reference)
#include <cuda_runtime.h>
#include <cstdint>

// out[n] = embedding[hash(trunc(x[n]*128))]  (reference's xf==0 collapses the
// trilerp to corner 0, weight 1; bit-exact).
// hash = (u0 ^ u1*2654435761 ^ u2*805459861) & (2^19 - 1)
//
// R4: break the gather's register scoreboard with cp.async.cg. Each lane pair
// fires the two 16B halves of one random 32B embedding row directly into a
// shared-memory output tile (no dest register -> no long-scoreboard stall,
// unbounded outstanding depth). After wait_group 0 + syncthreads the block
// streams the tile to gmem with fully coalesced LDS.128 -> STG.128.
// N = 2,097,152 = 512 * 4096 exactly -> no bounds checks.

static constexpr unsigned P1 = 2654435761u;
static constexpr unsigned P2 = 805459861u;
static constexpr unsigned HASH_MASK = 524288u - 1u;  // 2^19
static constexpr int THREADS = 256;
static constexpr int PTS_PER_BLOCK = 512;            // 128 pairs * 4 pts
static constexpr int PTS_PER_PAIR = 4;

__global__ void __launch_bounds__(THREADS)
hashgrid_cpasync_kernel(const float* __restrict__ x,
                        const char* __restrict__ emb,   // [H] rows of 32B
                        float4* __restrict__ out)       // [N*2] float4
{
    __shared__ __align__(16) char tile[PTS_PER_BLOCK * 32];  // 16 KB

    const int tid  = threadIdx.x;
    const int pid  = tid >> 1;        // pair index 0..127
    const int half = tid & 1;         // which 16B half of the row

    const int base = blockIdx.x * PTS_PER_BLOCK;

    // ---- phase 1: x loads (front-batched), hashes, cp.async gathers ----
    float xv[PTS_PER_PAIR][3];
#pragma unroll
    for (int k = 0; k < PTS_PER_PAIR; k++) {
        int p = base + pid + 128 * k;
        xv[k][0] = __ldg(&x[3 * p + 0]);
        xv[k][1] = __ldg(&x[3 * p + 1]);
        xv[k][2] = __ldg(&x[3 * p + 2]);
    }

    unsigned smem_base;
    asm("{ .reg .u64 t; cvta.to.shared.u64 t, %1; cvt.u32.u64 %0, t; }"
        : "=r"(smem_base) : "l"(tile));

#pragma unroll
    for (int k = 0; k < PTS_PER_PAIR; k++) {
        unsigned u0 = (unsigned)__float2int_rz(xv[k][0] * 128.0f);
        unsigned u1 = (unsigned)__float2int_rz(xv[k][1] * 128.0f);
        unsigned u2 = (unsigned)__float2int_rz(xv[k][2] * 128.0f);
        unsigned h  = (u0 ^ (u1 * P1) ^ (u2 * P2)) & HASH_MASK;

        int pl = pid + 128 * k;  // local point slot
        unsigned dst = smem_base + (unsigned)(pl * 32 + half * 16);
        const char* src = emb + ((size_t)h * 32u + (unsigned)(half * 16));
        asm volatile("cp.async.cg.shared.global [%0], [%1], 16;\n"
                     :: "r"(dst), "l"(src));
    }
    asm volatile("cp.async.commit_group;\n");
    asm volatile("cp.async.wait_group 0;\n");
    __syncthreads();

    // ---- phase 2: coalesced tile flush (1024 float4 per block) ----
    const float4* t4 = (const float4*)tile;
    float4* o4 = out + (size_t)base * 2;
#pragma unroll
    for (int k = 0; k < 4; k++)
        o4[tid + 256 * k] = t4[tid + 256 * k];
}

extern "C" void kernel_launch(void* const* d_in, const int* in_sizes, int n_in,
                              void* d_out, int out_size)
{
    const float* x   = (const float*)d_in[0];
    const char*  emb = (const char*)d_in[1];
    float4*      out = (float4*)d_out;

    int n = in_sizes[0] / 3;                    // N_POINTS (2,097,152)
    int blocks = n / PTS_PER_BLOCK;             // exact: 4096
    hashgrid_cpasync_kernel<<<blocks, THREADS>>>(x, emb, out);
}

// round 7
// speedup vs baseline: 1.0638x; 1.0638x over previous
#include <cuda_runtime.h>
#include <cstdint>

// out[n] = embedding[hash(trunc(x[n]*128))]  (reference's xf==0 collapses the
// trilerp to corner 0, weight 1; bit-exact).
// hash = (u0 ^ u1*2654435761 ^ u2*805459861) & (2^19 - 1)
//
// R7: hybrid gather. The LDG/L1tex path is walled at ~0.35 random lines/cyc/SM
// (R2-R4 all plateau ~22.5us); gather4 traps on sm_103a tensormap constraints.
// Instead split each 1024-pt block: 512 pts via plain non-tensor
// cp.async.bulk (UBLKCP, 32B per point, no tensormap, TMA engine -> smem,
// bypasses the L1 fill queue), 512 pts via the proven LDG pair-gather.
// Bulk ops issue first so both engines run concurrently.

static constexpr unsigned P1 = 2654435761u;
static constexpr unsigned P2 = 805459861u;
static constexpr unsigned HASH_MASK = 524288u - 1u;  // 2^19
static constexpr int THREADS = 256;
static constexpr int PTS_PER_BLOCK = 1024;
static constexpr int HALF_PTS = 512;

__device__ __forceinline__ unsigned hash3f(float a, float b, float c)
{
    unsigned u0 = (unsigned)__float2int_rz(a * 128.0f);
    unsigned u1 = (unsigned)__float2int_rz(b * 128.0f);
    unsigned u2 = (unsigned)__float2int_rz(c * 128.0f);
    return (u0 ^ (u1 * P1) ^ (u2 * P2)) & HASH_MASK;
}

__global__ void __launch_bounds__(THREADS)
hashgrid_hybrid_kernel(const float* __restrict__ x,
                       const float4* __restrict__ emb,   // [H][2] float4
                       float4* __restrict__ out)         // [N][2] float4
{
    __shared__ __align__(128) float4 tile[HALF_PTS * 2];  // 16 KB
    __shared__ __align__(8) unsigned long long mbar;

    const int tid = threadIdx.x;
    const size_t base  = (size_t)blockIdx.x * PTS_PER_BLOCK;
    const size_t tbase = base + HALF_PTS;  // bulk-gathered half

    unsigned bar_a  = (unsigned)__cvta_generic_to_shared(&mbar);
    unsigned tile_a = (unsigned)__cvta_generic_to_shared(tile);

    if (tid == 0) {
        asm volatile("mbarrier.init.shared.b64 [%0], 1;" :: "r"(bar_a) : "memory");
        // expect_tx BEFORE syncthreads so it's ordered before any bulk op.
        asm volatile("mbarrier.arrive.expect_tx.shared.b64 _, [%0], %1;"
                     :: "r"(bar_a), "r"(HALF_PTS * 32) : "memory");
    }
    __syncthreads();

    // ---- phase 1: issue 2 bulk 32B gathers per thread (TMA engine) ----
#pragma unroll
    for (int k = 0; k < 2; k++) {
        size_t p = tbase + (size_t)tid + 256 * k;
        float a = __ldg(&x[3 * p + 0]);
        float b = __ldg(&x[3 * p + 1]);
        float c = __ldg(&x[3 * p + 2]);
        unsigned h = hash3f(a, b, c);
        const void* src = (const char*)emb + (size_t)h * 32u;
        unsigned dst = tile_a + (unsigned)(tid + 256 * k) * 32u;
        asm volatile(
            "cp.async.bulk.shared::cta.global.mbarrier::complete_tx::bytes "
            "[%0], [%1], 32, [%2];"
            :: "r"(dst), "l"(src), "r"(bar_a) : "memory");
    }

    // ---- phase 2: LDG pair-gather half (proven R3 path), overlaps TMA ----
    {
        int w    = tid >> 5;
        int lane = tid & 31;
        int qw   = lane >> 1;
        int half = lane & 1;
        size_t pb = base + (size_t)w * 64 + qw;

        float xv[4][3];
#pragma unroll
        for (int k = 0; k < 4; k++) {
            size_t p = pb + 16 * k;
            xv[k][0] = x[3 * p + 0];
            xv[k][1] = x[3 * p + 1];
            xv[k][2] = x[3 * p + 2];
        }
        unsigned h[4];
#pragma unroll
        for (int k = 0; k < 4; k++)
            h[k] = hash3f(xv[k][0], xv[k][1], xv[k][2]);

        float4 v[4];
#pragma unroll
        for (int k = 0; k < 4; k++)
            v[k] = __ldcg(&emb[2 * h[k] + half]);
#pragma unroll
        for (int k = 0; k < 4; k++) {
            size_t p = pb + 16 * k;
            out[2 * p + half] = v[k];
        }
    }

    // ---- phase 3: wait for bulk half, flush tile coalesced ----
    asm volatile(
        "{\n\t"
        ".reg .pred P;\n\t"
        "WAIT_%=:\n\t"
        "mbarrier.try_wait.parity.acquire.cta.shared::cta.b64 P, [%0], 0, 0x989680;\n\t"
        "@P bra.uni DONE_%=;\n\t"
        "bra.uni WAIT_%=;\n\t"
        "DONE_%=:\n\t"
        "}"
        :: "r"(bar_a) : "memory");

    float4* o4 = out + tbase * 2;
#pragma unroll
    for (int k = 0; k < 4; k++)
        o4[tid + 256 * k] = tile[tid + 256 * k];
}

// ---------------- fallback (proven R3) for non-multiple sizes ----------------

__global__ void __launch_bounds__(THREADS)
hashgrid_gather_ilp4_kernel(const float* __restrict__ x,
                            const float4* __restrict__ emb,
                            float4* __restrict__ out,
                            int n)
{
    int tid  = threadIdx.x;
    int w    = tid >> 5;
    int lane = tid & 31;
    int qw   = lane >> 1;
    int half = lane & 1;
    int base = blockIdx.x * 512 + w * 64 + qw;

    float xv[4][3];
#pragma unroll
    for (int k = 0; k < 4; k++) {
        int p = base + 16 * k;
        if (p < n) {
            xv[k][0] = x[3 * p + 0];
            xv[k][1] = x[3 * p + 1];
            xv[k][2] = x[3 * p + 2];
        }
    }
    unsigned h[4];
#pragma unroll
    for (int k = 0; k < 4; k++)
        h[k] = hash3f(xv[k][0], xv[k][1], xv[k][2]);

    float4 v[4];
#pragma unroll
    for (int k = 0; k < 4; k++)
        if (base + 16 * k < n) v[k] = __ldg(&emb[2 * h[k] + half]);
#pragma unroll
    for (int k = 0; k < 4; k++) {
        int p = base + 16 * k;
        if (p < n) out[2 * p + half] = v[k];
    }
}

extern "C" void kernel_launch(void* const* d_in, const int* in_sizes, int n_in,
                              void* d_out, int out_size)
{
    const float*  x   = (const float*)d_in[0];
    const float4* emb = (const float4*)d_in[1];
    float4*       out = (float4*)d_out;

    int n = in_sizes[0] / 3;  // N_POINTS

    if (n % PTS_PER_BLOCK == 0) {
        int blocks = n / PTS_PER_BLOCK;  // 2048
        hashgrid_hybrid_kernel<<<blocks, THREADS>>>(x, emb, out);
    } else {
        int blocks = (n + 511) / 512;
        hashgrid_gather_ilp4_kernel<<<blocks, THREADS>>>(x, emb, out, n);
    }
}